// round 6
// baseline (speedup 1.0000x reference)
#include <cuda_runtime.h>
#include <math_constants.h>

#define BATCH 8
#define NPTS  4096
#define KNN   20
#define KSW   32
#define RPW   4                         // rows per warp
#define WARPS 8
#define THREADS 256
#define ROWS_PER_BLOCK (RPW * WARPS)    // 32
#define FULL 0xffffffffu
#define IDX_COUNT (BATCH * NPTS * KNN)

// pd = RN( RN(-xx_j + 2*dot) - xx_i ), dot = sequential FMA chain over f
// (reference broadcast order; 2*dot exact so fmaf == RN(-xxj - inner)).
__device__ __forceinline__ float pdist(const float4 pi, const float nxxi, const float4 pj)
{
    float d = fmaf(pi.z, pj.z, fmaf(pi.y, pj.y, __fmul_rn(pi.x, pj.x)));
    return __fadd_rn(fmaf(2.0f, d, -pj.w), nxxi);
}

// Order-isomorphic float<->uint maps (larger float <-> larger uint).
__device__ __forceinline__ unsigned enc(float f)
{
    int v = __float_as_int(f);
    return (unsigned)(v ^ ((v >> 31) | 0x80000000));
}
__device__ __forceinline__ float dec(unsigned uu)
{
    int m = ((int)uu) >> 31;                       // top set -> 0xFFFFFFFF
    return __int_as_float((int)(uu ^ ((~(unsigned)m) | 0x80000000u)));
}

// Insert qualifying candidates of one 32-batch into the unsorted distributed
// top-20 (one entry/lane; lanes>=20 hold 0xFFFFFFFF sentinels, never min).
// Exact semantics: evict unique worst by (pd asc, j desc); strict '>' keeps
// smaller-j incumbent on ties (candidates arrive in ascending j).
__device__ __forceinline__ void events(unsigned qm, const float pdc, const int jbase,
                                       unsigned& u, int& idx,
                                       unsigned& minu, float& tvf, const int lane)
{
    while (qm) {
        const int s = __ffs(qm) - 1;
        qm &= qm - 1;
        const unsigned uc = enc(__shfl_sync(FULL, pdc, s));
        if (uc > minu) {                            // warp-uniform
            const int jc = jbase + s;
            unsigned em = __ballot_sync(FULL, u == minu);
            if (em & (em - 1)) {                    // duplicated min: evict largest j
                int jv = (u == minu) ? idx : -1;
                int jmax = __reduce_max_sync(FULL, jv);
                em = __ballot_sync(FULL, jv == jmax);
            }
            const int ev = __ffs(em) - 1;
            if (lane == ev) { u = uc; idx = jc; }
            minu = __reduce_min_sync(FULL, u);
            tvf  = dec(minu);
        }
    }
}

// Bitonic sort of 32 (u, j) across the warp, (u desc, j asc). Pairs distinct.
__device__ __forceinline__ void bitonic32(unsigned& u, int& j, const int lane)
{
#pragma unroll
    for (int k = 2; k <= 32; k <<= 1) {
#pragma unroll
        for (int s = k >> 1; s > 0; s >>= 1) {
            unsigned ou = __shfl_xor_sync(FULL, u, s);
            int       oj = __shfl_xor_sync(FULL, j, s);
            bool ob = (ou > u) || (ou == u && oj < j);
            bool up = ((lane & k) == 0) == ((lane & s) == 0);
            if (up ? ob : !ob) { u = ou; j = oj; }
        }
    }
}

__device__ __forceinline__ void epilogue(const float4* __restrict__ sp,
                                         float* __restrict__ out,
                                         const float k0, const float k1, const float k2,
                                         const int b, const int i, const int idx,
                                         const int lane)
{
    const int grow = b * NPTS + i;

    if (lane < KNN)
        out[(size_t)grow * KNN + lane] = (float)(b * NPTS + idx);

    int nb[KNN];
#pragma unroll
    for (int kk = 0; kk < KNN; ++kk)
        nb[kk] = __shfl_sync(FULL, idx, kk);

    const float4 q0 = sp[nb[0]];
    float w[KNN];
#pragma unroll
    for (int kk = 0; kk < KNN; ++kk) {
        float4 qj = sp[nb[kk]];
        float e0 = qj.x - q0.x;
        float e1 = qj.y - q0.y;
        float e2 = qj.z - q0.z;
        float vv = fmaf(e2, k2, fmaf(e1, k1, __fmul_rn(e0, k0)));
        if (kk == 0 && lane == 0) vv = __fadd_rn(vv, 1.0f);  // one_padding[0][0]
        w[kk] = vv;
    }

    float s1 = 0.0f;
#pragma unroll
    for (int kk = 0; kk < KNN; ++kk) {
        float t = w[kk] > 0.0f ? w[kk] : 0.0f;
        w[kk] = t;
        s1 = __fadd_rn(s1, t);
    }
    const float den1 = __fadd_rn(s1, 1e-6f);
    float s2 = 0.0f;
#pragma unroll
    for (int kk = 0; kk < KNN; ++kk) {
        float t = __fdiv_rn(w[kk], den1);
        t = __fmul_rn(t, t);
        w[kk] = t;
        s2 = __fadd_rn(s2, t);
    }
    const float den2 = __fadd_rn(s2, 1e-6f);

    float* ow = out + IDX_COUNT + (size_t)grow * (KNN * KSW);
#pragma unroll
    for (int kk = 0; kk < KNN; ++kk) {
        float t = __fdiv_rn(w[kk], den2);
        ow[kk * KSW + lane] = (t > 0.1f) ? t : 0.0f;
    }
}

__global__ __launch_bounds__(THREADS, 3)
void pai_knn_kernel(const float* __restrict__ x,
                    const float* __restrict__ kern,
                    float* __restrict__ out)
{
    extern __shared__ float4 sp[];   // NPTS entries: (x, y, z, ||p||^2)

    const int b    = blockIdx.x >> 7;               // 128 blocks per batch
    const int row0 = (blockIdx.x & 127) * ROWS_PER_BLOCK;
    const float* xb = x + (size_t)b * 3 * NPTS;

    for (int t = threadIdx.x; t < NPTS; t += THREADS) {
        float a0 = xb[t];
        float a1 = xb[NPTS + t];
        float a2 = xb[2 * NPTS + t];
        float xx = __fadd_rn(__fadd_rn(__fmul_rn(a0, a0), __fmul_rn(a1, a1)),
                             __fmul_rn(a2, a2));
        sp[t] = make_float4(a0, a1, a2, xx);
    }
    __syncthreads();

    const int warp = threadIdx.x >> 5;
    const int lane = threadIdx.x & 31;

    float4   pi[RPW];
    float    nxxi[RPW];
    unsigned u[RPW];
    int      idx[RPW];
    unsigned minu[RPW];
    float    tvf[RPW];
    int      rowi[RPW];

#pragma unroll
    for (int r = 0; r < RPW; ++r) {
        rowi[r] = row0 + warp + r * WARPS;
        pi[r]   = sp[rowi[r]];
        nxxi[r] = -pi[r].w;
    }

    // ---- Peel chunk 0 (candidates 0..127): seed lists from j=0..19, then events.
    {
        float4 p0 = sp[lane];
        float4 p1 = sp[32 + lane];
        float4 p2 = sp[64 + lane];
        float4 p3 = sp[96 + lane];
#pragma unroll
        for (int r = 0; r < RPW; ++r) {
            float a0 = pdist(pi[r], nxxi[r], p0);
            u[r]    = (lane < KNN) ? enc(a0) : 0xFFFFFFFFu;
            idx[r]  = (lane < KNN) ? lane : 0x7FFFFFFF;
            minu[r] = __reduce_min_sync(FULL, u[r]);
            tvf[r]  = dec(minu[r]);
            unsigned qm = __ballot_sync(FULL, (lane >= KNN) && (a0 > tvf[r]));
            events(qm, a0, 0, u[r], idx[r], minu[r], tvf[r], lane);

            float a1 = pdist(pi[r], nxxi[r], p1);
            events(__ballot_sync(FULL, a1 > tvf[r]), a1, 32, u[r], idx[r], minu[r], tvf[r], lane);
            float a2 = pdist(pi[r], nxxi[r], p2);
            events(__ballot_sync(FULL, a2 > tvf[r]), a2, 64, u[r], idx[r], minu[r], tvf[r], lane);
            float a3 = pdist(pi[r], nxxi[r], p3);
            events(__ballot_sync(FULL, a3 > tvf[r]), a3, 96, u[r], idx[r], minu[r], tvf[r], lane);
        }
    }

    // ---- Main scan: one shared 128-candidate load serves all 4 rows.
#pragma unroll 1
    for (int it = 1; it < NPTS / 128; ++it) {
        const int jb = it * 128;
        float4 p0 = sp[jb + lane];
        float4 p1 = sp[jb + 32 + lane];
        float4 p2 = sp[jb + 64 + lane];
        float4 p3 = sp[jb + 96 + lane];

#pragma unroll
        for (int r = 0; r < RPW; ++r) {
            float a0 = pdist(pi[r], nxxi[r], p0);
            events(__ballot_sync(FULL, a0 > tvf[r]), a0, jb,      u[r], idx[r], minu[r], tvf[r], lane);
            float a1 = pdist(pi[r], nxxi[r], p1);
            events(__ballot_sync(FULL, a1 > tvf[r]), a1, jb + 32, u[r], idx[r], minu[r], tvf[r], lane);
            float a2 = pdist(pi[r], nxxi[r], p2);
            events(__ballot_sync(FULL, a2 > tvf[r]), a2, jb + 64, u[r], idx[r], minu[r], tvf[r], lane);
            float a3 = pdist(pi[r], nxxi[r], p3);
            events(__ballot_sync(FULL, a3 > tvf[r]), a3, jb + 96, u[r], idx[r], minu[r], tvf[r], lane);
        }
    }

    // ---- Sort each row's set (sentinels -> 0 so they sort last) + epilogue.
    const float k0 = kern[lane];
    const float k1 = kern[KSW + lane];
    const float k2 = kern[2 * KSW + lane];

#pragma unroll
    for (int r = 0; r < RPW; ++r) {
        unsigned su = (lane < KNN || u[r] != 0xFFFFFFFFu) ? u[r] : 0u;
        // (all real entries are in lanes arbitrary; sentinels are exactly the
        //  0xFFFFFFFF values — no real pd encodes to 0xFFFFFFFF (= +NaN))
        if (u[r] == 0xFFFFFFFFu) { su = 0u; idx[r] = 0x7FFFFFFF; }
        unsigned uu = su; int jj = idx[r];
        bitonic32(uu, jj, lane);
        epilogue(sp, out, k0, k1, k2, b, rowi[r], jj, lane);
    }
}

extern "C" void kernel_launch(void* const* d_in, const int* in_sizes, int n_in,
                              void* d_out, int out_size)
{
    const float* x    = (const float*)d_in[0];
    const float* kern = (const float*)d_in[1];

    (void)in_sizes; (void)n_in; (void)out_size;

    cudaFuncSetAttribute(pai_knn_kernel,
                         cudaFuncAttributeMaxDynamicSharedMemorySize,
                         NPTS * sizeof(float4));

    dim3 grid(BATCH * (NPTS / ROWS_PER_BLOCK));   // 1024 blocks
    pai_knn_kernel<<<grid, THREADS, NPTS * sizeof(float4)>>>(x, kern, (float*)d_out);
}

// round 7
// speedup vs baseline: 1.4318x; 1.4318x over previous
#include <cuda_runtime.h>
#include <math_constants.h>

#define BATCH 8
#define NPTS  4096
#define KNN   20
#define KSW   32
#define ROWS_PER_BLOCK 32     // 16 warps x 2 rows
#define THREADS 512
#define FULL 0xffffffffu

#define IDX_COUNT (BATCH * NPTS * KNN)

// pd = RN( RN(-xx_j + 2*dot) - xx_i ), dot = sequential FMA chain over f.
// (reference broadcast order; 2*dot exact so fmaf == RN(-xxj - inner)).
__device__ __forceinline__ float pdist(const float4 pi, const float nxxi, const float4 pj)
{
    float d = fmaf(pi.z, pj.z, fmaf(pi.y, pj.y, __fmul_rn(pi.x, pj.x)));
    return __fadd_rn(fmaf(2.0f, d, -pj.w), nxxi);
}

// Full bitonic sort of 32 (v, j) pairs across the warp, descending by
// (v desc, j asc on ties). j values are distinct, so no full ties.
__device__ __forceinline__ void bitonic32(float& v, int& j, const int lane)
{
#pragma unroll
    for (int k = 2; k <= 32; k <<= 1) {
#pragma unroll
        for (int s = k >> 1; s > 0; s >>= 1) {
            float ov = __shfl_xor_sync(FULL, v, s);
            int   oj = __shfl_xor_sync(FULL, j, s);
            bool ob = (ov > v) || (ov == v && oj < j);   // other is better
            bool up = ((lane & k) == 0) == ((lane & s) == 0);
            if (up ? ob : !ob) { v = ov; j = oj; }
        }
    }
}

// Process one 32-candidate batch against a warp-distributed sorted top-20
// (lane t<20 holds t-th best). Exact tie-break (pd desc, j asc): candidates
// arrive in globally ascending j; insertion uses (pc>v)||(pc==v && jc<idx).
// tv is refreshed once per batch-with-events: within a batch tv is not
// consumed (qm is fixed at entry), so this is bit-exact and cheaper.
__device__ __forceinline__ void processBatch(const float pdc, const int jbase,
                                             float& v, int& idx, float& tv,
                                             const int lane)
{
    unsigned qm = __ballot_sync(FULL, pdc >= tv);
    if (qm) {
        do {
            const int s = __ffs(qm) - 1;
            qm &= qm - 1;
            const float pc = __shfl_sync(FULL, pdc, s);
            const int   jc = jbase + s;

            float vu = __shfl_up_sync(FULL, v,   1);
            int   iu = __shfl_up_sync(FULL, idx, 1);
            bool take = (pc > v) || (pc == v && jc < idx);
            unsigned bt = __ballot_sync(FULL, take) & 0xFFFFFu;
            const int p = __ffs(bt) - 1;     // -1 when bt==0 -> no lane matches
            if (take) {                       // predicated, no extra BSSY region
                bool at = (lane == p);
                v   = at ? pc : vu;
                idx = at ? jc : iu;
            }
        } while (qm);
        tv = __shfl_sync(FULL, v, 19);
    }
}

__device__ __forceinline__ void epilogue(const float4* __restrict__ sp,
                                         float* __restrict__ out,
                                         const float k0, const float k1, const float k2,
                                         const int b, const int i, const int idx,
                                         const int lane)
{
    const int grow = b * NPTS + i;

    // Output 1: spirals_index (as float); lane t<20 already holds the t-th.
    if (lane < KNN)
        out[(size_t)grow * KNN + lane] = (float)(b * NPTS + idx);

    int nb[KNN];
#pragma unroll
    for (int kk = 0; kk < KNN; ++kk)
        nb[kk] = __shfl_sync(FULL, idx, kk);

    const float4 q0 = sp[nb[0]];
    float w[KNN];
#pragma unroll
    for (int kk = 0; kk < KNN; ++kk) {
        float4 qj = sp[nb[kk]];
        float e0 = qj.x - q0.x;
        float e1 = qj.y - q0.y;
        float e2 = qj.z - q0.z;
        float vv = fmaf(e2, k2, fmaf(e1, k1, __fmul_rn(e0, k0)));
        if (kk == 0 && lane == 0) vv = __fadd_rn(vv, 1.0f);  // one_padding[0][0]
        w[kk] = vv;
    }

    // _top_max over the k axis (per ks column == per lane)
    float s1 = 0.0f;
#pragma unroll
    for (int kk = 0; kk < KNN; ++kk) {
        float t = w[kk] > 0.0f ? w[kk] : 0.0f;
        w[kk] = t;
        s1 = __fadd_rn(s1, t);
    }
    const float den1 = __fadd_rn(s1, 1e-6f);
    float s2 = 0.0f;
#pragma unroll
    for (int kk = 0; kk < KNN; ++kk) {
        float t = __fdiv_rn(w[kk], den1);
        t = __fmul_rn(t, t);
        w[kk] = t;
        s2 = __fadd_rn(s2, t);
    }
    const float den2 = __fadd_rn(s2, 1e-6f);

    float* ow = out + IDX_COUNT + (size_t)grow * (KNN * KSW);
#pragma unroll
    for (int kk = 0; kk < KNN; ++kk) {
        float t = __fdiv_rn(w[kk], den2);
        ow[kk * KSW + lane] = (t > 0.1f) ? t : 0.0f;
    }
}

__global__ __launch_bounds__(THREADS, 2)
void pai_knn_kernel(const float* __restrict__ x,
                    const float* __restrict__ kern,
                    float* __restrict__ out)
{
    extern __shared__ float4 sp[];   // NPTS entries: (x, y, z, ||p||^2)

    const int b    = blockIdx.x >> 7;               // 128 blocks per batch
    const int row0 = (blockIdx.x & 127) * ROWS_PER_BLOCK;
    const float* xb = x + (size_t)b * 3 * NPTS;

    // Stage batch points: xx = ((x0^2 + x1^2) + x2^2), plain mul/add chain.
    for (int t = threadIdx.x; t < NPTS; t += THREADS) {
        float a0 = xb[t];
        float a1 = xb[NPTS + t];
        float a2 = xb[2 * NPTS + t];
        float xx = __fadd_rn(__fadd_rn(__fmul_rn(a0, a0), __fmul_rn(a1, a1)),
                             __fmul_rn(a2, a2));
        sp[t] = make_float4(a0, a1, a2, xx);
    }
    __syncthreads();

    const int warp = threadIdx.x >> 5;
    const int lane = threadIdx.x & 31;
    const int iA   = row0 + warp;          // row A
    const int iB   = iA + 16;              // row B

    const float4 piA = sp[iA];  const float nxxiA = -piA.w;
    const float4 piB = sp[iB];  const float nxxiB = -piB.w;

    // ---- Peel candidates 0..127: bitonic seed on 0..31, ballot on the rest.
    float4 p0 = sp[lane];
    float4 p1 = sp[32 + lane];
    float4 p2 = sp[64 + lane];
    float4 p3 = sp[96 + lane];

    float a0 = pdist(piA, nxxiA, p0), a1 = pdist(piA, nxxiA, p1);
    float a2 = pdist(piA, nxxiA, p2), a3 = pdist(piA, nxxiA, p3);
    float b0 = pdist(piB, nxxiB, p0), b1 = pdist(piB, nxxiB, p1);
    float b2 = pdist(piB, nxxiB, p2), b3 = pdist(piB, nxxiB, p3);

    float vA = a0; int idxA = lane;
    bitonic32(vA, idxA, lane);
    float tvA = __shfl_sync(FULL, vA, 19);

    float vB = b0; int idxB = lane;
    bitonic32(vB, idxB, lane);
    float tvB = __shfl_sync(FULL, vB, 19);

    processBatch(a1, 32, vA, idxA, tvA, lane);
    processBatch(b1, 32, vB, idxB, tvB, lane);
    processBatch(a2, 64, vA, idxA, tvA, lane);
    processBatch(b2, 64, vB, idxB, tvB, lane);
    processBatch(a3, 96, vA, idxA, tvA, lane);
    processBatch(b3, 96, vB, idxB, tvB, lane);

    // ---- Main scan: shared candidate loads serve both rows; A/B interleaved.
#pragma unroll 1
    for (int it = 1; it < NPTS / 128; ++it) {
        const int jb = it * 128;
        p0 = sp[jb + lane];
        p1 = sp[jb + 32 + lane];
        p2 = sp[jb + 64 + lane];
        p3 = sp[jb + 96 + lane];

        a0 = pdist(piA, nxxiA, p0); a1 = pdist(piA, nxxiA, p1);
        a2 = pdist(piA, nxxiA, p2); a3 = pdist(piA, nxxiA, p3);
        b0 = pdist(piB, nxxiB, p0); b1 = pdist(piB, nxxiB, p1);
        b2 = pdist(piB, nxxiB, p2); b3 = pdist(piB, nxxiB, p3);

        processBatch(a0, jb,      vA, idxA, tvA, lane);
        processBatch(b0, jb,      vB, idxB, tvB, lane);
        processBatch(a1, jb + 32, vA, idxA, tvA, lane);
        processBatch(b1, jb + 32, vB, idxB, tvB, lane);
        processBatch(a2, jb + 64, vA, idxA, tvA, lane);
        processBatch(b2, jb + 64, vB, idxB, tvB, lane);
        processBatch(a3, jb + 96, vA, idxA, tvA, lane);
        processBatch(b3, jb + 96, vB, idxB, tvB, lane);
    }

    const float k0 = kern[lane];
    const float k1 = kern[KSW + lane];
    const float k2 = kern[2 * KSW + lane];

    epilogue(sp, out, k0, k1, k2, b, iA, idxA, lane);
    epilogue(sp, out, k0, k1, k2, b, iB, idxB, lane);
}

extern "C" void kernel_launch(void* const* d_in, const int* in_sizes, int n_in,
                              void* d_out, int out_size)
{
    const float* x    = (const float*)d_in[0];
    const float* kern = (const float*)d_in[1];

    (void)in_sizes; (void)n_in; (void)out_size;

    cudaFuncSetAttribute(pai_knn_kernel,
                         cudaFuncAttributeMaxDynamicSharedMemorySize,
                         NPTS * sizeof(float4));

    dim3 grid(BATCH * (NPTS / ROWS_PER_BLOCK));   // 1024 blocks
    pai_knn_kernel<<<grid, THREADS, NPTS * sizeof(float4)>>>(x, kern, (float*)d_out);
}